// round 6
// baseline (speedup 1.0000x reference)
#include <cuda_runtime.h>

#define NN 100000
#define NE 1600000
#define NG 1000
#define F1 64
#define F2 128
#define P0 8          // padded width of layer-0 features (6 used)
#define SCAN_B 1024
#define NB_SCAN ((NN + SCAN_B - 1) / SCAN_B)   // 98

// Scratch (device globals — no allocation allowed)
__device__ int   d_hist[NN];      // in-degree (dst occurrences)
__device__ int   d_row[NN];       // CSR row start (exclusive scan of hist)
__device__ int   d_cur[NN];       // fill cursors
__device__ int   d_bsum[NB_SCAN];
__device__ int   d_csr[NE];       // src ids grouped by dst
__device__ float d_dinv[NN];
__device__ __align__(16) float d_p0[NN * P0];    // dinv * x (padded)
__device__ __align__(16) float d_acc0[NN * P0];  // aggregated (incl self)
__device__ __align__(16) float d_p1[NN * F1];    // dinv * relu(out1)
__device__ __align__(16) float d_acc1[NN * F1];  // aggregated (incl self)
__device__ __align__(16) float d_pool[NG * F2];
__device__ float d_cntf[NG];

__device__ __forceinline__ float relu(float v) { return v > 0.f ? v : 0.f; }

// ---------------------------------------------------------------------------
// 0) Zero hist / pool / cnt
// ---------------------------------------------------------------------------
__global__ void k_init() {
    int i = blockIdx.x * blockDim.x + threadIdx.x;
    if (i < NN)      d_hist[i] = 0;
    if (i < NG * F2) d_pool[i] = 0.f;
    if (i < NG)      d_cntf[i] = 0.f;
}

// ---------------------------------------------------------------------------
// 1) Histogram of dst (in-degree), int atomics
// ---------------------------------------------------------------------------
__global__ void k_hist(const int* __restrict__ ei) {
    int i = blockIdx.x * blockDim.x + threadIdx.x;
    if (i < NE) atomicAdd(&d_hist[ei[NE + i]], 1);
}

// ---------------------------------------------------------------------------
// 2) Exclusive scan of hist -> row  (block scan + serial block-sum scan + fix)
// ---------------------------------------------------------------------------
__global__ void k_scan1() {
    __shared__ int s[SCAN_B];
    int i = blockIdx.x * SCAN_B + threadIdx.x;
    int v = (i < NN) ? d_hist[i] : 0;
    s[threadIdx.x] = v;
    __syncthreads();
    for (int off = 1; off < SCAN_B; off <<= 1) {
        int t = (threadIdx.x >= off) ? s[threadIdx.x - off] : 0;
        __syncthreads();
        s[threadIdx.x] += t;
        __syncthreads();
    }
    if (i < NN) d_row[i] = s[threadIdx.x] - v;  // exclusive, pre-offset
    if (threadIdx.x == SCAN_B - 1) d_bsum[blockIdx.x] = s[SCAN_B - 1];
}

__global__ void k_scan2() {
    int a = 0;
    for (int b = 0; b < NB_SCAN; b++) { int t = d_bsum[b]; d_bsum[b] = a; a += t; }
}

__global__ void k_scan3() {
    int i = blockIdx.x * blockDim.x + threadIdx.x;
    if (i < NN) {
        int r = d_row[i] + d_bsum[i >> 10];
        d_row[i] = r;
        d_cur[i] = r;
        d_dinv[i] = rsqrtf((float)d_hist[i] + 1.f);  // +1 self loop
    }
}

// ---------------------------------------------------------------------------
// 3) CSR fill: csr[pos] = src, grouped by dst
// ---------------------------------------------------------------------------
__global__ void k_fill(const int* __restrict__ ei) {
    int e = blockIdx.x * blockDim.x + threadIdx.x;
    if (e >= NE) return;
    int s = ei[e];
    int d = ei[NE + e];
    int pos = atomicAdd(&d_cur[d], 1);
    d_csr[pos] = s;
}

// ---------------------------------------------------------------------------
// 4) p0[v] = dinv[v] * x[v]   (6 floats, padded to 8)
// ---------------------------------------------------------------------------
__global__ void k_p0(const float* __restrict__ x) {
    int n = blockIdx.x * blockDim.x + threadIdx.x;
    if (n >= NN) return;
    float dv = d_dinv[n];
    float4 a, b;
    a.x = dv * x[n * 6 + 0];
    a.y = dv * x[n * 6 + 1];
    a.z = dv * x[n * 6 + 2];
    a.w = dv * x[n * 6 + 3];
    b.x = dv * x[n * 6 + 4];
    b.y = dv * x[n * 6 + 5];
    b.z = 0.f; b.w = 0.f;
    *reinterpret_cast<float4*>(&d_p0[n * P0 + 0]) = a;
    *reinterpret_cast<float4*>(&d_p0[n * P0 + 4]) = b;
}

// ---------------------------------------------------------------------------
// 5) PULL layer 0: acc0[n] = p0[n] + sum_{s in in(n)} p0[s]   (no atomics)
//    One thread per node, 2 float4 accumulators.
// ---------------------------------------------------------------------------
__global__ void k_pull0() {
    int n = blockIdx.x * blockDim.x + threadIdx.x;
    if (n >= NN) return;
    int start = d_row[n];
    int deg   = d_hist[n];
    float4 a = *reinterpret_cast<const float4*>(&d_p0[n * P0 + 0]);
    float4 b = *reinterpret_cast<const float4*>(&d_p0[n * P0 + 4]);
    for (int j = 0; j < deg; j++) {
        int s = d_csr[start + j];
        float4 u = *reinterpret_cast<const float4*>(&d_p0[s * P0 + 0]);
        float4 w = *reinterpret_cast<const float4*>(&d_p0[s * P0 + 4]);
        a.x += u.x; a.y += u.y; a.z += u.z; a.w += u.w;
        b.x += w.x; b.y += w.y; b.z += w.z; b.w += w.w;
    }
    *reinterpret_cast<float4*>(&d_acc0[n * P0 + 0]) = a;
    *reinterpret_cast<float4*>(&d_acc0[n * P0 + 4]) = b;
}

// ---------------------------------------------------------------------------
// 6) out1 = relu(dinv*(acc0@W1) + b1);  p1 = dinv * out1
//    16 threads/node, each computes 4 features.
// ---------------------------------------------------------------------------
__global__ void k_l1(const float* __restrict__ W1, const float* __restrict__ b1) {
    __shared__ float w[6 * F1];
    for (int j = threadIdx.x; j < 6 * F1; j += blockDim.x) w[j] = W1[j];
    __syncthreads();
    int i = blockIdx.x * blockDim.x + threadIdx.x;
    if (i >= NN * 16) return;
    int n = i >> 4;
    int c = (i & 15) * 4;
    float dv = d_dinv[n];
    float t[6];
#pragma unroll
    for (int k = 0; k < 6; k++) t[k] = d_acc0[n * P0 + k];
    float4 o;
    float* po = (float*)&o;
#pragma unroll
    for (int j = 0; j < 4; j++) {
        float a = 0.f;
#pragma unroll
        for (int k = 0; k < 6; k++) a += t[k] * w[k * F1 + c + j];
        po[j] = dv * relu(dv * a + b1[c + j]);
    }
    *reinterpret_cast<float4*>(&d_p1[n * F1 + c]) = o;
}

// ---------------------------------------------------------------------------
// 7) PULL layer 1: acc1[n] = p1[n] + sum_{s in in(n)} p1[s]   (no atomics)
//    One warp per node; lane covers feats {lane, lane+32}. Unroll-by-2 for MLP.
// ---------------------------------------------------------------------------
__global__ void k_pull1() {
    int wid  = (blockIdx.x * blockDim.x + threadIdx.x) >> 5;
    int lane = threadIdx.x & 31;
    if (wid >= NN) return;
    int n = wid;
    int start = d_row[n];
    int deg   = d_hist[n];
    float a0 = d_p1[n * F1 + lane];
    float a1 = d_p1[n * F1 + 32 + lane];
    int j = 0;
    for (; j + 2 <= deg; j += 2) {
        int s0 = d_csr[start + j];
        int s1 = d_csr[start + j + 1];
        float u0 = d_p1[s0 * F1 + lane];
        float u1 = d_p1[s0 * F1 + 32 + lane];
        float v0 = d_p1[s1 * F1 + lane];
        float v1 = d_p1[s1 * F1 + 32 + lane];
        a0 += u0 + v0;
        a1 += u1 + v1;
    }
    if (j < deg) {
        int s0 = d_csr[start + j];
        a0 += d_p1[s0 * F1 + lane];
        a1 += d_p1[s0 * F1 + 32 + lane];
    }
    d_acc1[n * F1 + lane]      = a0;
    d_acc1[n * F1 + 32 + lane] = a1;
}

// ---------------------------------------------------------------------------
// 8) out2 = relu(dinv*(acc1@W2) + b2); pool[batch[n]] += out2; cnt += 1
//    128 threads/block (one out feature each), 16 nodes per block.
// ---------------------------------------------------------------------------
__global__ void k_l2pool(const float* __restrict__ W2, const float* __restrict__ b2,
                         const int* __restrict__ batch) {
    __shared__ float w[F1 * F2];
    __shared__ float in_s[F1];
    int tid = threadIdx.x;
    for (int j = tid; j < F1 * F2; j += 128) w[j] = W2[j];
    int base = blockIdx.x * 16;
    for (int t = 0; t < 16; t++) {
        int n = base + t;
        float dv = d_dinv[n];
        __syncthreads();
        if (tid < F1) in_s[tid] = d_acc1[n * F1 + tid];
        __syncthreads();
        float a = 0.f;
#pragma unroll
        for (int k = 0; k < F1; k++) a += in_s[k] * w[k * F2 + tid];
        float v = relu(dv * a + b2[tid]);
        int gid = batch[n];
        atomicAdd(&d_pool[gid * F2 + tid], v);
        if (tid == 0) atomicAdd(&d_cntf[gid], 1.f);
    }
}

// ---------------------------------------------------------------------------
// 9) out[g] = (pool[g]/max(cnt,1)) @ Wfc + bfc      [1000, 2]
// ---------------------------------------------------------------------------
__global__ void k_fc(const float* __restrict__ Wfc, const float* __restrict__ bfc,
                     float* __restrict__ out) {
    int i = blockIdx.x * blockDim.x + threadIdx.x;
    if (i >= NG * 2) return;
    int g = i >> 1;
    int o = i & 1;
    float cnt = d_cntf[g];
    float inv = 1.f / (cnt > 1.f ? cnt : 1.f);
    float a = 0.f;
#pragma unroll 8
    for (int k = 0; k < F2; k++) a += d_pool[g * F2 + k] * Wfc[k * 2 + o];
    out[i] = a * inv + bfc[o];
}

// ---------------------------------------------------------------------------
extern "C" void kernel_launch(void* const* d_in, const int* in_sizes, int n_in,
                              void* d_out, int out_size) {
    const float* x   = (const float*)d_in[0];
    const int*   ei  = (const int*)d_in[1];   // int32 (JAX x64 disabled)
    const int*   bat = (const int*)d_in[2];   // int32
    const float* W1  = (const float*)d_in[3];
    const float* b1  = (const float*)d_in[4];
    const float* W2  = (const float*)d_in[5];
    const float* b2  = (const float*)d_in[6];
    const float* Wfc = (const float*)d_in[7];
    const float* bfc = (const float*)d_in[8];
    float*       out = (float*)d_out;

    k_init <<<(NG * F2 + 255) / 256, 256>>>();
    k_hist <<<(NE + 255) / 256, 256>>>(ei);
    k_scan1<<<NB_SCAN, SCAN_B>>>();
    k_scan2<<<1, 1>>>();
    k_scan3<<<(NN + 255) / 256, 256>>>();
    k_fill <<<(NE + 255) / 256, 256>>>(ei);
    k_p0   <<<(NN + 255) / 256, 256>>>(x);
    k_pull0<<<(NN + 255) / 256, 256>>>();
    k_l1   <<<(NN * 16 + 255) / 256, 256>>>(W1, b1);
    k_pull1<<<(NN * 8 * 32 + 255) / 256, 256>>>();
    k_l2pool<<<NN / 16, 128>>>(W2, b2, bat);
    k_fc   <<<(NG * 2 + 255) / 256, 256>>>(Wfc, bfc, out);
}

// round 7
// speedup vs baseline: 1.6761x; 1.6761x over previous
#include <cuda_runtime.h>

#define NN 100000
#define NE 1600000
#define NG 1000
#define F1 64
#define F2 128
#define P0 8          // padded width of layer-0 features (6 used)
#define SCAN_B 1024
#define NB_SCAN ((NN + SCAN_B - 1) / SCAN_B)   // 98

// Scratch (device globals — no allocation allowed)
__device__ int   d_hist[NN];      // in-degree (dst occurrences)
__device__ int   d_row[NN];       // CSR row start (exclusive scan of hist)
__device__ int   d_cur[NN];       // fill cursors
__device__ int   d_bsum[NB_SCAN];
__device__ int   d_csr[NE];       // src ids grouped by dst
__device__ float d_dinv[NN];
__device__ __align__(16) float d_p0[NN * P0];    // dinv * x (padded)
__device__ __align__(16) float d_acc0[NN * P0];  // aggregated (incl self)
__device__ __align__(16) float d_p1[NN * F1];    // dinv * relu(out1)
__device__ __align__(16) float d_acc1[NN * F1];  // aggregated (incl self)
__device__ __align__(16) float d_pool[NG * F2];
__device__ float d_cntf[NG];

__device__ __forceinline__ float relu(float v) { return v > 0.f ? v : 0.f; }

// ---------------------------------------------------------------------------
// 0) Zero hist / pool / cnt
// ---------------------------------------------------------------------------
__global__ void k_init() {
    int i = blockIdx.x * blockDim.x + threadIdx.x;
    if (i < NN)      d_hist[i] = 0;
    if (i < NG * F2) d_pool[i] = 0.f;
    if (i < NG)      d_cntf[i] = 0.f;
}

// ---------------------------------------------------------------------------
// 1) Histogram of dst (in-degree), int atomics
// ---------------------------------------------------------------------------
__global__ void k_hist(const int* __restrict__ ei) {
    int i = blockIdx.x * blockDim.x + threadIdx.x;
    if (i < NE) atomicAdd(&d_hist[ei[NE + i]], 1);
}

// ---------------------------------------------------------------------------
// 2) Exclusive scan of hist -> row
// ---------------------------------------------------------------------------
__global__ void k_scan1() {
    __shared__ int s[SCAN_B];
    int i = blockIdx.x * SCAN_B + threadIdx.x;
    int v = (i < NN) ? d_hist[i] : 0;
    s[threadIdx.x] = v;
    __syncthreads();
    for (int off = 1; off < SCAN_B; off <<= 1) {
        int t = (threadIdx.x >= off) ? s[threadIdx.x - off] : 0;
        __syncthreads();
        s[threadIdx.x] += t;
        __syncthreads();
    }
    if (i < NN) d_row[i] = s[threadIdx.x] - v;  // exclusive, pre-offset
    if (threadIdx.x == SCAN_B - 1) d_bsum[blockIdx.x] = s[SCAN_B - 1];
}

__global__ void k_scan2() {   // 1 block, 128 threads: scan 98 block sums
    __shared__ int s[128];
    int v = (threadIdx.x < NB_SCAN) ? d_bsum[threadIdx.x] : 0;
    s[threadIdx.x] = v;
    __syncthreads();
    for (int off = 1; off < 128; off <<= 1) {
        int t = (threadIdx.x >= off) ? s[threadIdx.x - off] : 0;
        __syncthreads();
        s[threadIdx.x] += t;
        __syncthreads();
    }
    if (threadIdx.x < NB_SCAN) d_bsum[threadIdx.x] = s[threadIdx.x] - v;  // exclusive
}

__global__ void k_scan3() {
    int i = blockIdx.x * blockDim.x + threadIdx.x;
    if (i < NN) {
        int r = d_row[i] + d_bsum[i >> 10];
        d_row[i] = r;
        d_cur[i] = r;
        d_dinv[i] = rsqrtf((float)d_hist[i] + 1.f);  // +1 self loop
    }
}

// ---------------------------------------------------------------------------
// 3) CSR fill: csr[pos] = src, grouped by dst
// ---------------------------------------------------------------------------
__global__ void k_fill(const int* __restrict__ ei) {
    int e = blockIdx.x * blockDim.x + threadIdx.x;
    if (e >= NE) return;
    int s = ei[e];
    int d = ei[NE + e];
    int pos = atomicAdd(&d_cur[d], 1);
    d_csr[pos] = s;
}

// ---------------------------------------------------------------------------
// 4) p0[v] = dinv[v] * x[v]  + graph node counts (batch sorted, low contention)
// ---------------------------------------------------------------------------
__global__ void k_p0(const float* __restrict__ x, const int* __restrict__ batch) {
    int n = blockIdx.x * blockDim.x + threadIdx.x;
    if (n >= NN) return;
    float dv = d_dinv[n];
    float4 a, b;
    a.x = dv * x[n * 6 + 0];
    a.y = dv * x[n * 6 + 1];
    a.z = dv * x[n * 6 + 2];
    a.w = dv * x[n * 6 + 3];
    b.x = dv * x[n * 6 + 4];
    b.y = dv * x[n * 6 + 5];
    b.z = 0.f; b.w = 0.f;
    *reinterpret_cast<float4*>(&d_p0[n * P0 + 0]) = a;
    *reinterpret_cast<float4*>(&d_p0[n * P0 + 4]) = b;
    atomicAdd(&d_cntf[batch[n]], 1.f);
}

// ---------------------------------------------------------------------------
// 5) PULL layer 0: acc0[n] = p0[n] + sum_{s in in(n)} p0[s]
// ---------------------------------------------------------------------------
__global__ void k_pull0() {
    int n = blockIdx.x * blockDim.x + threadIdx.x;
    if (n >= NN) return;
    int start = d_row[n];
    int deg   = d_hist[n];
    float4 a = *reinterpret_cast<const float4*>(&d_p0[n * P0 + 0]);
    float4 b = *reinterpret_cast<const float4*>(&d_p0[n * P0 + 4]);
    for (int j = 0; j < deg; j++) {
        int s = d_csr[start + j];
        float4 u = *reinterpret_cast<const float4*>(&d_p0[s * P0 + 0]);
        float4 w = *reinterpret_cast<const float4*>(&d_p0[s * P0 + 4]);
        a.x += u.x; a.y += u.y; a.z += u.z; a.w += u.w;
        b.x += w.x; b.y += w.y; b.z += w.z; b.w += w.w;
    }
    *reinterpret_cast<float4*>(&d_acc0[n * P0 + 0]) = a;
    *reinterpret_cast<float4*>(&d_acc0[n * P0 + 4]) = b;
}

// ---------------------------------------------------------------------------
// 6) out1 = relu(dinv*(acc0@W1) + b1);  p1 = dinv * out1
// ---------------------------------------------------------------------------
__global__ void k_l1(const float* __restrict__ W1, const float* __restrict__ b1) {
    __shared__ float w[6 * F1];
    for (int j = threadIdx.x; j < 6 * F1; j += blockDim.x) w[j] = W1[j];
    __syncthreads();
    int i = blockIdx.x * blockDim.x + threadIdx.x;
    if (i >= NN * 16) return;
    int n = i >> 4;
    int c = (i & 15) * 4;
    float dv = d_dinv[n];
    float t[6];
#pragma unroll
    for (int k = 0; k < 6; k++) t[k] = d_acc0[n * P0 + k];
    float4 o;
    float* po = (float*)&o;
#pragma unroll
    for (int j = 0; j < 4; j++) {
        float a = 0.f;
#pragma unroll
        for (int k = 0; k < 6; k++) a += t[k] * w[k * F1 + c + j];
        po[j] = dv * relu(dv * a + b1[c + j]);
    }
    *reinterpret_cast<float4*>(&d_p1[n * F1 + c]) = o;
}

// ---------------------------------------------------------------------------
// 7) PULL layer 1: acc1[n] = p1[n] + sum_{s in in(n)} p1[s]
//    One warp per node; lane covers feats {lane, lane+32}.
// ---------------------------------------------------------------------------
__global__ void k_pull1() {
    int wid  = (blockIdx.x * blockDim.x + threadIdx.x) >> 5;
    int lane = threadIdx.x & 31;
    if (wid >= NN) return;
    int n = wid;
    int start = d_row[n];
    int deg   = d_hist[n];
    float a0 = d_p1[n * F1 + lane];
    float a1 = d_p1[n * F1 + 32 + lane];
    int j = 0;
    for (; j + 2 <= deg; j += 2) {
        int s0 = d_csr[start + j];
        int s1 = d_csr[start + j + 1];
        float u0 = d_p1[s0 * F1 + lane];
        float u1 = d_p1[s0 * F1 + 32 + lane];
        float v0 = d_p1[s1 * F1 + lane];
        float v1 = d_p1[s1 * F1 + 32 + lane];
        a0 += u0 + v0;
        a1 += u1 + v1;
    }
    if (j < deg) {
        int s0 = d_csr[start + j];
        a0 += d_p1[s0 * F1 + lane];
        a1 += d_p1[s0 * F1 + 32 + lane];
    }
    d_acc1[n * F1 + lane]      = a0;
    d_acc1[n * F1 + 32 + lane] = a1;
}

// ---------------------------------------------------------------------------
// 8) out2 = relu(dinv*(acc1@W2) + b2); pooled into d_pool.
//    W2 column in REGISTERS (64/thread); 16 nodes staged in smem per block;
//    batch sorted -> register pool accumulator, flush on graph change.
// ---------------------------------------------------------------------------
__global__ void k_l2pool(const float* __restrict__ W2, const float* __restrict__ b2,
                         const int* __restrict__ batch) {
    __shared__ float in_s[16][F1];       // 4 KB
    int tid = threadIdx.x;               // 0..127 = output feature
    float wcol[F1];
#pragma unroll
    for (int k = 0; k < F1; k++) wcol[k] = W2[k * F2 + tid];
    float bb = b2[tid];
    int base = blockIdx.x * 16;
    for (int i = tid; i < 16 * F1; i += 128)
        in_s[i >> 6][i & 63] = d_acc1[base * F1 + i];
    __syncthreads();
    float pacc = 0.f;
    int cgid = batch[base];
    for (int t = 0; t < 16; t++) {
        int n = base + t;
        int gid = batch[n];
        if (gid != cgid) {
            atomicAdd(&d_pool[cgid * F2 + tid], pacc);
            pacc = 0.f;
            cgid = gid;
        }
        float dv = d_dinv[n];
        float a = 0.f;
#pragma unroll
        for (int k = 0; k < F1; k++) a += in_s[t][k] * wcol[k];
        pacc += relu(dv * a + bb);
    }
    atomicAdd(&d_pool[cgid * F2 + tid], pacc);
}

// ---------------------------------------------------------------------------
// 9) out[g] = (pool[g]/max(cnt,1)) @ Wfc + bfc      [1000, 2]
// ---------------------------------------------------------------------------
__global__ void k_fc(const float* __restrict__ Wfc, const float* __restrict__ bfc,
                     float* __restrict__ out) {
    int i = blockIdx.x * blockDim.x + threadIdx.x;
    if (i >= NG * 2) return;
    int g = i >> 1;
    int o = i & 1;
    float cnt = d_cntf[g];
    float inv = 1.f / (cnt > 1.f ? cnt : 1.f);
    float a = 0.f;
#pragma unroll 8
    for (int k = 0; k < F2; k++) a += d_pool[g * F2 + k] * Wfc[k * 2 + o];
    out[i] = a * inv + bfc[o];
}

// ---------------------------------------------------------------------------
extern "C" void kernel_launch(void* const* d_in, const int* in_sizes, int n_in,
                              void* d_out, int out_size) {
    const float* x   = (const float*)d_in[0];
    const int*   ei  = (const int*)d_in[1];   // int32 (JAX x64 disabled)
    const int*   bat = (const int*)d_in[2];   // int32
    const float* W1  = (const float*)d_in[3];
    const float* b1  = (const float*)d_in[4];
    const float* W2  = (const float*)d_in[5];
    const float* b2  = (const float*)d_in[6];
    const float* Wfc = (const float*)d_in[7];
    const float* bfc = (const float*)d_in[8];
    float*       out = (float*)d_out;

    k_init <<<(NG * F2 + 255) / 256, 256>>>();
    k_hist <<<(NE + 255) / 256, 256>>>(ei);
    k_scan1<<<NB_SCAN, SCAN_B>>>();
    k_scan2<<<1, 128>>>();
    k_scan3<<<(NN + 255) / 256, 256>>>();
    k_fill <<<(NE + 255) / 256, 256>>>(ei);
    k_p0   <<<(NN + 255) / 256, 256>>>(x, bat);
    k_pull0<<<(NN + 255) / 256, 256>>>();
    k_l1   <<<(NN * 16 + 255) / 256, 256>>>(W1, b1);
    k_pull1<<<(NN * 32 + 255) / 256, 256>>>();
    k_l2pool<<<NN / 16, 128>>>(W2, b2, bat);
    k_fc   <<<(NG * 2 + 255) / 256, 256>>>(Wfc, bfc, out);
}

// round 8
// speedup vs baseline: 1.8016x; 1.0748x over previous
#include <cuda_runtime.h>

#define NN 100000
#define NE 1600000
#define NG 1000
#define F1 64
#define F2 128
#define P0 8          // padded width of layer-0 features (6 used)
#define SCAN_B 1024
#define NB_SCAN ((NN + SCAN_B - 1) / SCAN_B)   // 98

// Scratch (device globals — no allocation allowed)
__device__ int   d_hist[NN];
__device__ int   d_row[NN];
__device__ int   d_cur[NN];
__device__ int   d_bsum[NB_SCAN];
__device__ int   d_csr[NE];
__device__ float d_dinv[NN];
__device__ __align__(16) float d_p0[NN * P0];
__device__ __align__(16) float d_p1[NN * F1];
__device__ __align__(16) float d_acc1[NN * F1];
__device__ __align__(16) float d_pool[NG * F2];
__device__ float d_cntf[NG];

__device__ __forceinline__ float relu(float v) { return v > 0.f ? v : 0.f; }

// ---------------------------------------------------------------------------
// 0) Zero hist / pool / cnt
// ---------------------------------------------------------------------------
__global__ void k_init() {
    int i = blockIdx.x * blockDim.x + threadIdx.x;
    if (i < NN)      d_hist[i] = 0;
    if (i < NG * F2) d_pool[i] = 0.f;
    if (i < NG)      d_cntf[i] = 0.f;
}

// ---------------------------------------------------------------------------
// 1) Histogram of dst (in-degree), int atomics; 4 edges/thread via int4
// ---------------------------------------------------------------------------
__global__ void k_hist(const int* __restrict__ ei) {
    int i = blockIdx.x * blockDim.x + threadIdx.x;   // edge-quad index
    if (i * 4 >= NE) return;
    int4 d4 = *reinterpret_cast<const int4*>(&ei[NE + i * 4]);
    atomicAdd(&d_hist[d4.x], 1);
    atomicAdd(&d_hist[d4.y], 1);
    atomicAdd(&d_hist[d4.z], 1);
    atomicAdd(&d_hist[d4.w], 1);
}

// ---------------------------------------------------------------------------
// 2) Per-block exclusive scan of hist -> row (pre-offset) + block sums
// ---------------------------------------------------------------------------
__global__ void k_scan1() {
    __shared__ int s[SCAN_B];
    int i = blockIdx.x * SCAN_B + threadIdx.x;
    int v = (i < NN) ? d_hist[i] : 0;
    s[threadIdx.x] = v;
    __syncthreads();
    for (int off = 1; off < SCAN_B; off <<= 1) {
        int t = (threadIdx.x >= off) ? s[threadIdx.x - off] : 0;
        __syncthreads();
        s[threadIdx.x] += t;
        __syncthreads();
    }
    if (i < NN) d_row[i] = s[threadIdx.x] - v;
    if (threadIdx.x == SCAN_B - 1) d_bsum[blockIdx.x] = s[SCAN_B - 1];
}

// ---------------------------------------------------------------------------
// 3) Fused: redundant per-block scan of bsum + finalize row/cur/dinv
//    + p0 = dinv*x + per-graph node counts.
// ---------------------------------------------------------------------------
__global__ void k_scan3p0(const float* __restrict__ x, const int* __restrict__ batch) {
    __shared__ int s[128];
    int tid = threadIdx.x;                       // block = 256 threads
    if (tid < 128) {
        int v = (tid < NB_SCAN) ? d_bsum[tid] : 0;
        s[tid] = v;
        __syncthreads();
        for (int off = 1; off < 128; off <<= 1) {
            int t = (tid >= off) ? s[tid - off] : 0;
            __syncthreads();
            s[tid] += t;
            __syncthreads();
        }
        s[tid] -= v;                             // exclusive
    } else {
        for (int off = 1; off < 128; off <<= 1) { __syncthreads(); __syncthreads(); }
    }
    __syncthreads();
    int n = blockIdx.x * blockDim.x + tid;
    if (n >= NN) return;
    int r = d_row[n] + s[n >> 10];
    d_row[n] = r;
    d_cur[n] = r;
    float dv = rsqrtf((float)d_hist[n] + 1.f);   // +1 self loop
    d_dinv[n] = dv;
    float4 a, b;
    a.x = dv * x[n * 6 + 0];
    a.y = dv * x[n * 6 + 1];
    a.z = dv * x[n * 6 + 2];
    a.w = dv * x[n * 6 + 3];
    b.x = dv * x[n * 6 + 4];
    b.y = dv * x[n * 6 + 5];
    b.z = 0.f; b.w = 0.f;
    *reinterpret_cast<float4*>(&d_p0[n * P0 + 0]) = a;
    *reinterpret_cast<float4*>(&d_p0[n * P0 + 4]) = b;
    atomicAdd(&d_cntf[batch[n]], 1.f);
}

// ---------------------------------------------------------------------------
// 4) CSR fill: csr[pos] = src, grouped by dst; 4 edges/thread via int4
// ---------------------------------------------------------------------------
__global__ void k_fill(const int* __restrict__ ei) {
    int i = blockIdx.x * blockDim.x + threadIdx.x;
    if (i * 4 >= NE) return;
    int4 s4 = *reinterpret_cast<const int4*>(&ei[i * 4]);
    int4 d4 = *reinterpret_cast<const int4*>(&ei[NE + i * 4]);
    d_csr[atomicAdd(&d_cur[d4.x], 1)] = s4.x;
    d_csr[atomicAdd(&d_cur[d4.y], 1)] = s4.y;
    d_csr[atomicAdd(&d_cur[d4.z], 1)] = s4.z;
    d_csr[atomicAdd(&d_cur[d4.w], 1)] = s4.w;
}

// ---------------------------------------------------------------------------
// 5) Fused PULL0 + L1: t = p0[n] + sum_in p0[s];
//    p1 = dinv * relu(dinv*(t@W1) + b1).  One thread per node.
// ---------------------------------------------------------------------------
__global__ void k_pull0l1(const float* __restrict__ W1, const float* __restrict__ b1) {
    __shared__ float w[6 * F1];
    __shared__ float bs[F1];
    for (int j = threadIdx.x; j < 6 * F1; j += blockDim.x) w[j] = W1[j];
    if (threadIdx.x < F1) bs[threadIdx.x] = b1[threadIdx.x];
    __syncthreads();
    int n = blockIdx.x * blockDim.x + threadIdx.x;
    if (n >= NN) return;
    int start = d_row[n];
    int deg   = d_hist[n];
    float4 a = *reinterpret_cast<const float4*>(&d_p0[n * P0 + 0]);
    float4 b = *reinterpret_cast<const float4*>(&d_p0[n * P0 + 4]);
    for (int j = 0; j < deg; j++) {
        int s = d_csr[start + j];
        float4 u = *reinterpret_cast<const float4*>(&d_p0[s * P0 + 0]);
        float4 v = *reinterpret_cast<const float4*>(&d_p0[s * P0 + 4]);
        a.x += u.x; a.y += u.y; a.z += u.z; a.w += u.w;
        b.x += v.x; b.y += v.y;
    }
    float t[6] = {a.x, a.y, a.z, a.w, b.x, b.y};
    float dv = d_dinv[n];
#pragma unroll
    for (int j = 0; j < 16; j++) {
        float4 o;
        float* po = (float*)&o;
#pragma unroll
        for (int c = 0; c < 4; c++) {
            int idx = j * 4 + c;
            float acc = 0.f;
#pragma unroll
            for (int k = 0; k < 6; k++) acc += t[k] * w[k * F1 + idx];
            po[c] = dv * relu(dv * acc + bs[idx]);
        }
        *reinterpret_cast<float4*>(&d_p1[n * F1 + j * 4]) = o;
    }
}

// ---------------------------------------------------------------------------
// 6) PULL layer 1: acc1[n] = p1[n] + sum_in p1[s].  Warp per node,
//    lane covers feats {lane, lane+32}; unroll-by-4 for MLP.
// ---------------------------------------------------------------------------
__global__ void k_pull1() {
    int wid  = (blockIdx.x * blockDim.x + threadIdx.x) >> 5;
    int lane = threadIdx.x & 31;
    if (wid >= NN) return;
    int n = wid;
    int start = d_row[n];
    int deg   = d_hist[n];
    float a0 = d_p1[n * F1 + lane];
    float a1 = d_p1[n * F1 + 32 + lane];
    int j = 0;
    for (; j + 4 <= deg; j += 4) {
        int s0 = d_csr[start + j];
        int s1 = d_csr[start + j + 1];
        int s2 = d_csr[start + j + 2];
        int s3 = d_csr[start + j + 3];
        float u0 = d_p1[s0 * F1 + lane];
        float u1 = d_p1[s0 * F1 + 32 + lane];
        float v0 = d_p1[s1 * F1 + lane];
        float v1 = d_p1[s1 * F1 + 32 + lane];
        float w0 = d_p1[s2 * F1 + lane];
        float w1 = d_p1[s2 * F1 + 32 + lane];
        float x0 = d_p1[s3 * F1 + lane];
        float x1 = d_p1[s3 * F1 + 32 + lane];
        a0 += (u0 + v0) + (w0 + x0);
        a1 += (u1 + v1) + (w1 + x1);
    }
    for (; j < deg; j++) {
        int s0 = d_csr[start + j];
        a0 += d_p1[s0 * F1 + lane];
        a1 += d_p1[s0 * F1 + 32 + lane];
    }
    d_acc1[n * F1 + lane]      = a0;
    d_acc1[n * F1 + 32 + lane] = a1;
}

// ---------------------------------------------------------------------------
// 7) out2 = relu(dinv*(acc1@W2) + b2), pooled.  Packed f32x2: two NODES in
//    the two lanes; weights duplicated (w,w) in regs; inner = LDS.128 + 2 FFMA2.
//    128 threads = one output feature each; 16 nodes (8 pairs) per block.
// ---------------------------------------------------------------------------
__global__ void k_l2pool(const float* __restrict__ W2, const float* __restrict__ b2,
                         const int* __restrict__ batch) {
    __shared__ float2 inp[8][F1];      // node-pair packed inputs, 4 KB
    __shared__ float dv_s[16];
    __shared__ int   bt_s[16];
    int tid = threadIdx.x;             // output feature
    unsigned long long wp[F1];
#pragma unroll
    for (int k = 0; k < F1; k++) {
        float wv = W2[k * F2 + tid];
        asm("mov.b64 %0, {%1, %1};" : "=l"(wp[k]) : "f"(wv));
    }
    float bb = b2[tid];
    int base = blockIdx.x * 16;
    for (int i = tid; i < 16 * F1; i += 128) {
        int nl = i >> 6, k = i & 63;
        reinterpret_cast<float*>(&inp[nl >> 1][k])[nl & 1] = d_acc1[(base + nl) * F1 + k];
    }
    if (tid < 16) {
        dv_s[tid] = d_dinv[base + tid];
        bt_s[tid] = batch[base + tid];
    }
    __syncthreads();
    float pacc = 0.f;
    int cgid = bt_s[0];
#pragma unroll
    for (int p = 0; p < 8; p++) {
        unsigned long long acc = 0ull;   // (0.f, 0.f)
        const ulonglong2* ip = reinterpret_cast<const ulonglong2*>(&inp[p][0]);
#pragma unroll
        for (int k = 0; k < F1; k += 2) {
            ulonglong2 pv = ip[k >> 1];  // LDS.128 broadcast (2 packed k's)
            asm("fma.rn.f32x2 %0, %1, %2, %3;" : "=l"(acc) : "l"(wp[k]),     "l"(pv.x), "l"(acc));
            asm("fma.rn.f32x2 %0, %1, %2, %3;" : "=l"(acc) : "l"(wp[k + 1]), "l"(pv.y), "l"(acc));
        }
        float a0, a1;
        asm("mov.b64 {%0, %1}, %2;" : "=f"(a0), "=f"(a1) : "l"(acc));
        int n0 = 2 * p, n1 = 2 * p + 1;
        int g0 = bt_s[n0];
        if (g0 != cgid) { atomicAdd(&d_pool[cgid * F2 + tid], pacc); pacc = 0.f; cgid = g0; }
        pacc += relu(dv_s[n0] * a0 + bb);
        int g1 = bt_s[n1];
        if (g1 != cgid) { atomicAdd(&d_pool[cgid * F2 + tid], pacc); pacc = 0.f; cgid = g1; }
        pacc += relu(dv_s[n1] * a1 + bb);
    }
    atomicAdd(&d_pool[cgid * F2 + tid], pacc);
}

// ---------------------------------------------------------------------------
// 8) out[g] = (pool[g]/max(cnt,1)) @ Wfc + bfc      [1000, 2]
// ---------------------------------------------------------------------------
__global__ void k_fc(const float* __restrict__ Wfc, const float* __restrict__ bfc,
                     float* __restrict__ out) {
    int i = blockIdx.x * blockDim.x + threadIdx.x;
    if (i >= NG * 2) return;
    int g = i >> 1;
    int o = i & 1;
    float cnt = d_cntf[g];
    float inv = 1.f / (cnt > 1.f ? cnt : 1.f);
    float a = 0.f;
#pragma unroll 8
    for (int k = 0; k < F2; k++) a += d_pool[g * F2 + k] * Wfc[k * 2 + o];
    out[i] = a * inv + bfc[o];
}

// ---------------------------------------------------------------------------
extern "C" void kernel_launch(void* const* d_in, const int* in_sizes, int n_in,
                              void* d_out, int out_size) {
    const float* x   = (const float*)d_in[0];
    const int*   ei  = (const int*)d_in[1];   // int32 (JAX x64 disabled)
    const int*   bat = (const int*)d_in[2];   // int32
    const float* W1  = (const float*)d_in[3];
    const float* b1  = (const float*)d_in[4];
    const float* W2  = (const float*)d_in[5];
    const float* b2  = (const float*)d_in[6];
    const float* Wfc = (const float*)d_in[7];
    const float* bfc = (const float*)d_in[8];
    float*       out = (float*)d_out;

    k_init   <<<(NG * F2 + 255) / 256, 256>>>();
    k_hist   <<<(NE / 4 + 255) / 256, 256>>>(ei);
    k_scan1  <<<NB_SCAN, SCAN_B>>>();
    k_scan3p0<<<(NN + 255) / 256, 256>>>(x, bat);
    k_fill   <<<(NE / 4 + 255) / 256, 256>>>(ei);
    k_pull0l1<<<(NN + 255) / 256, 256>>>(W1, b1);
    k_pull1  <<<(NN * 32 + 255) / 256, 256>>>();
    k_l2pool <<<NN / 16, 128>>>(W2, b2, bat);
    k_fc     <<<(NG * 2 + 255) / 256, 256>>>(Wfc, bfc, out);
}

// round 9
// speedup vs baseline: 1.8424x; 1.0226x over previous
#include <cuda_runtime.h>

#define NN 100000
#define NE 1600000
#define NG 1000
#define F1 64
#define F2 128
#define P0 8
#define SCAN_B 1024
#define NB_SCAN ((NN + SCAN_B - 1) / SCAN_B)   // 98
#define NPB 80          // nodes per block in l2pool (100000/80 = 1250 exact)

// Scratch (device globals — no allocation allowed)
__device__ int   d_hist[NN];
__device__ int   d_row[NN];
__device__ int   d_cur[NN];
__device__ int   d_bsum[NB_SCAN];
__device__ int   d_csr[NE];
__device__ float d_dinv[NN];
__device__ __align__(16) float d_p0[NN * P0];
__device__ __align__(16) float d_p1[NN * F1];
__device__ __align__(16) float d_acc1[NN * F1];
__device__ __align__(16) float d_pool[NG * F2];
__device__ float d_cntf[NG];

__device__ __forceinline__ float relu(float v) { return v > 0.f ? v : 0.f; }

// ---------------------------------------------------------------------------
// 0) Zero hist / pool / cnt
// ---------------------------------------------------------------------------
__global__ void k_init() {
    int i = blockIdx.x * blockDim.x + threadIdx.x;
    if (i < NN)      d_hist[i] = 0;
    if (i < NG * F2) d_pool[i] = 0.f;
    if (i < NG)      d_cntf[i] = 0.f;
}

// ---------------------------------------------------------------------------
// 1) Histogram of dst (in-degree); 4 edges/thread via int4
// ---------------------------------------------------------------------------
__global__ void k_hist(const int* __restrict__ ei) {
    int i = blockIdx.x * blockDim.x + threadIdx.x;
    if (i * 4 >= NE) return;
    int4 d4 = *reinterpret_cast<const int4*>(&ei[NE + i * 4]);
    atomicAdd(&d_hist[d4.x], 1);
    atomicAdd(&d_hist[d4.y], 1);
    atomicAdd(&d_hist[d4.z], 1);
    atomicAdd(&d_hist[d4.w], 1);
}

// ---------------------------------------------------------------------------
// 2) Per-block exclusive scan of hist -> row (pre-offset) + block sums.
//    Shuffle scan: per-warp shfl + cross-warp fix (2 syncs total).
// ---------------------------------------------------------------------------
__global__ void k_scan1() {
    __shared__ int wsum[32];
    int tid  = threadIdx.x;              // 1024
    int lane = tid & 31, w = tid >> 5;
    int i = blockIdx.x * SCAN_B + tid;
    int v = (i < NN) ? d_hist[i] : 0;
    int incl = v;
#pragma unroll
    for (int off = 1; off < 32; off <<= 1) {
        int t = __shfl_up_sync(0xffffffffu, incl, off);
        if (lane >= off) incl += t;
    }
    if (lane == 31) wsum[w] = incl;
    __syncthreads();
    if (w == 0) {
        int s = wsum[lane];
        int si = s;
#pragma unroll
        for (int off = 1; off < 32; off <<= 1) {
            int t = __shfl_up_sync(0xffffffffu, si, off);
            if (lane >= off) si += t;
        }
        wsum[lane] = si - s;             // exclusive warp offsets
    }
    __syncthreads();
    int off = wsum[w];
    if (i < NN) d_row[i] = incl - v + off;
    if (tid == SCAN_B - 1) d_bsum[blockIdx.x] = off + incl;
}

// ---------------------------------------------------------------------------
// 3) Fused: redundant shfl-scan of the 98 block sums + finalize row/cur/dinv
//    + p0 = dinv*x + per-graph node counts.  (2 non-divergent syncs)
// ---------------------------------------------------------------------------
__global__ void k_scan3p0(const float* __restrict__ x, const int* __restrict__ batch) {
    __shared__ int wsum4[4];
    __shared__ int soff[128];
    int tid = threadIdx.x;               // 256
    int incl = 0, v = 0;
    if (tid < 128) {
        v = (tid < NB_SCAN) ? d_bsum[tid] : 0;
        incl = v;
        int lane = tid & 31;
#pragma unroll
        for (int off = 1; off < 32; off <<= 1) {
            int t = __shfl_up_sync(0xffffffffu, incl, off);
            if (lane >= off) incl += t;
        }
        if (lane == 31) wsum4[tid >> 5] = incl;
    }
    __syncthreads();
    if (tid < 128) {
        int w = tid >> 5;
        int add = 0;
#pragma unroll
        for (int k = 0; k < 4; k++) add += (k < w) ? wsum4[k] : 0;
        soff[tid] = incl - v + add;      // exclusive scan of bsum
    }
    __syncthreads();
    int n = blockIdx.x * blockDim.x + tid;
    if (n >= NN) return;
    int r = d_row[n] + soff[n >> 10];
    d_row[n] = r;
    d_cur[n] = r;
    float dv = rsqrtf((float)d_hist[n] + 1.f);   // +1 self loop
    d_dinv[n] = dv;
    float4 a, b;
    a.x = dv * x[n * 6 + 0];
    a.y = dv * x[n * 6 + 1];
    a.z = dv * x[n * 6 + 2];
    a.w = dv * x[n * 6 + 3];
    b.x = dv * x[n * 6 + 4];
    b.y = dv * x[n * 6 + 5];
    b.z = 0.f; b.w = 0.f;
    *reinterpret_cast<float4*>(&d_p0[n * P0 + 0]) = a;
    *reinterpret_cast<float4*>(&d_p0[n * P0 + 4]) = b;
    atomicAdd(&d_cntf[batch[n]], 1.f);
}

// ---------------------------------------------------------------------------
// 4) CSR fill: csr[pos] = src, grouped by dst; 4 edges/thread via int4
// ---------------------------------------------------------------------------
__global__ void k_fill(const int* __restrict__ ei) {
    int i = blockIdx.x * blockDim.x + threadIdx.x;
    if (i * 4 >= NE) return;
    int4 s4 = *reinterpret_cast<const int4*>(&ei[i * 4]);
    int4 d4 = *reinterpret_cast<const int4*>(&ei[NE + i * 4]);
    d_csr[atomicAdd(&d_cur[d4.x], 1)] = s4.x;
    d_csr[atomicAdd(&d_cur[d4.y], 1)] = s4.y;
    d_csr[atomicAdd(&d_cur[d4.z], 1)] = s4.z;
    d_csr[atomicAdd(&d_cur[d4.w], 1)] = s4.w;
}

// ---------------------------------------------------------------------------
// 5) Fused PULL0 + L1: t = p0[n] + sum_in p0[s];
//    p1 = dinv * relu(dinv*(t@W1) + b1).  One thread per node.
// ---------------------------------------------------------------------------
__global__ void k_pull0l1(const float* __restrict__ W1, const float* __restrict__ b1) {
    __shared__ float w[6 * F1];
    __shared__ float bs[F1];
    for (int j = threadIdx.x; j < 6 * F1; j += blockDim.x) w[j] = W1[j];
    if (threadIdx.x < F1) bs[threadIdx.x] = b1[threadIdx.x];
    __syncthreads();
    int n = blockIdx.x * blockDim.x + threadIdx.x;
    if (n >= NN) return;
    int start = d_row[n];
    int deg   = d_hist[n];
    float4 a = *reinterpret_cast<const float4*>(&d_p0[n * P0 + 0]);
    float4 b = *reinterpret_cast<const float4*>(&d_p0[n * P0 + 4]);
    for (int j = 0; j < deg; j++) {
        int s = d_csr[start + j];
        float4 u = *reinterpret_cast<const float4*>(&d_p0[s * P0 + 0]);
        float4 v = *reinterpret_cast<const float4*>(&d_p0[s * P0 + 4]);
        a.x += u.x; a.y += u.y; a.z += u.z; a.w += u.w;
        b.x += v.x; b.y += v.y;
    }
    float t[6] = {a.x, a.y, a.z, a.w, b.x, b.y};
    float dv = d_dinv[n];
#pragma unroll
    for (int j = 0; j < 16; j++) {
        float4 o;
        float* po = (float*)&o;
#pragma unroll
        for (int c = 0; c < 4; c++) {
            int idx = j * 4 + c;
            float acc = 0.f;
#pragma unroll
            for (int k = 0; k < 6; k++) acc += t[k] * w[k * F1 + idx];
            po[c] = dv * relu(dv * acc + bs[idx]);
        }
        *reinterpret_cast<float4*>(&d_p1[n * F1 + j * 4]) = o;
    }
}

// ---------------------------------------------------------------------------
// 6) PULL layer 1: acc1[n] = p1[n] + sum_in p1[s].  Warp per node,
//    lane covers feats {lane, lane+32}; unroll-by-4 for MLP.
// ---------------------------------------------------------------------------
__global__ void k_pull1() {
    int wid  = (blockIdx.x * blockDim.x + threadIdx.x) >> 5;
    int lane = threadIdx.x & 31;
    if (wid >= NN) return;
    int n = wid;
    int start = d_row[n];
    int deg   = d_hist[n];
    float a0 = d_p1[n * F1 + lane];
    float a1 = d_p1[n * F1 + 32 + lane];
    int j = 0;
    for (; j + 4 <= deg; j += 4) {
        int s0 = d_csr[start + j];
        int s1 = d_csr[start + j + 1];
        int s2 = d_csr[start + j + 2];
        int s3 = d_csr[start + j + 3];
        float u0 = d_p1[s0 * F1 + lane];
        float u1 = d_p1[s0 * F1 + 32 + lane];
        float v0 = d_p1[s1 * F1 + lane];
        float v1 = d_p1[s1 * F1 + 32 + lane];
        float w0 = d_p1[s2 * F1 + lane];
        float w1 = d_p1[s2 * F1 + 32 + lane];
        float x0 = d_p1[s3 * F1 + lane];
        float x1 = d_p1[s3 * F1 + 32 + lane];
        a0 += (u0 + v0) + (w0 + x0);
        a1 += (u1 + v1) + (w1 + x1);
    }
    for (; j < deg; j++) {
        int s0 = d_csr[start + j];
        a0 += d_p1[s0 * F1 + lane];
        a1 += d_p1[s0 * F1 + 32 + lane];
    }
    d_acc1[n * F1 + lane]      = a0;
    d_acc1[n * F1 + 32 + lane] = a1;
}

// ---------------------------------------------------------------------------
// 7) out2 = relu(dinv*(acc1@W2) + b2), pooled.  Packed f32x2 (two nodes per
//    lane-pair), weights duplicated in regs; 80 nodes/block to amortize the
//    32KB/block W2 reload (205MB -> 41MB of L2 weight traffic).
// ---------------------------------------------------------------------------
__global__ void k_l2pool(const float* __restrict__ W2, const float* __restrict__ b2,
                         const int* __restrict__ batch) {
    __shared__ float2 inp[NPB / 2][F1];   // 20 KB
    __shared__ float dv_s[NPB];
    __shared__ int   bt_s[NPB];
    int tid = threadIdx.x;                // output feature 0..127
    unsigned long long wp[F1];
#pragma unroll
    for (int k = 0; k < F1; k++) {
        float wv = W2[k * F2 + tid];
        asm("mov.b64 %0, {%1, %1};" : "=l"(wp[k]) : "f"(wv));
    }
    float bb = b2[tid];
    int base = blockIdx.x * NPB;
    for (int i = tid; i < NPB * F1; i += 128) {
        int nl = i >> 6, k = i & 63;
        reinterpret_cast<float*>(&inp[nl >> 1][k])[nl & 1] = d_acc1[(base + nl) * F1 + k];
    }
    if (tid < NPB) {
        dv_s[tid] = d_dinv[base + tid];
        bt_s[tid] = batch[base + tid];
    }
    __syncthreads();
    float pacc = 0.f;
    int cgid = bt_s[0];
    for (int p = 0; p < NPB / 2; p++) {
        unsigned long long acc = 0ull;    // (0.f, 0.f)
        const ulonglong2* ip = reinterpret_cast<const ulonglong2*>(&inp[p][0]);
#pragma unroll
        for (int k = 0; k < F1; k += 2) {
            ulonglong2 pv = ip[k >> 1];   // LDS.128: two packed k's
            asm("fma.rn.f32x2 %0, %1, %2, %3;" : "=l"(acc) : "l"(wp[k]),     "l"(pv.x), "l"(acc));
            asm("fma.rn.f32x2 %0, %1, %2, %3;" : "=l"(acc) : "l"(wp[k + 1]), "l"(pv.y), "l"(acc));
        }
        float a0, a1;
        asm("mov.b64 {%0, %1}, %2;" : "=f"(a0), "=f"(a1) : "l"(acc));
        int n0 = 2 * p, n1 = 2 * p + 1;
        int g0 = bt_s[n0];
        if (g0 != cgid) { atomicAdd(&d_pool[cgid * F2 + tid], pacc); pacc = 0.f; cgid = g0; }
        pacc += relu(dv_s[n0] * a0 + bb);
        int g1 = bt_s[n1];
        if (g1 != cgid) { atomicAdd(&d_pool[cgid * F2 + tid], pacc); pacc = 0.f; cgid = g1; }
        pacc += relu(dv_s[n1] * a1 + bb);
    }
    atomicAdd(&d_pool[cgid * F2 + tid], pacc);
}

// ---------------------------------------------------------------------------
// 8) out[g] = (pool[g]/max(cnt,1)) @ Wfc + bfc      [1000, 2]
// ---------------------------------------------------------------------------
__global__ void k_fc(const float* __restrict__ Wfc, const float* __restrict__ bfc,
                     float* __restrict__ out) {
    int i = blockIdx.x * blockDim.x + threadIdx.x;
    if (i >= NG * 2) return;
    int g = i >> 1;
    int o = i & 1;
    float cnt = d_cntf[g];
    float inv = 1.f / (cnt > 1.f ? cnt : 1.f);
    float a = 0.f;
#pragma unroll 8
    for (int k = 0; k < F2; k++) a += d_pool[g * F2 + k] * Wfc[k * 2 + o];
    out[i] = a * inv + bfc[o];
}

// ---------------------------------------------------------------------------
extern "C" void kernel_launch(void* const* d_in, const int* in_sizes, int n_in,
                              void* d_out, int out_size) {
    const float* x   = (const float*)d_in[0];
    const int*   ei  = (const int*)d_in[1];   // int32 (JAX x64 disabled)
    const int*   bat = (const int*)d_in[2];   // int32
    const float* W1  = (const float*)d_in[3];
    const float* b1  = (const float*)d_in[4];
    const float* W2  = (const float*)d_in[5];
    const float* b2  = (const float*)d_in[6];
    const float* Wfc = (const float*)d_in[7];
    const float* bfc = (const float*)d_in[8];
    float*       out = (float*)d_out;

    k_init   <<<(NG * F2 + 255) / 256, 256>>>();
    k_hist   <<<(NE / 4 + 255) / 256, 256>>>(ei);
    k_scan1  <<<NB_SCAN, SCAN_B>>>();
    k_scan3p0<<<(NN + 255) / 256, 256>>>(x, bat);
    k_fill   <<<(NE / 4 + 255) / 256, 256>>>(ei);
    k_pull0l1<<<(NN + 255) / 256, 256>>>(W1, b1);
    k_pull1  <<<(NN * 32 + 255) / 256, 256>>>();
    k_l2pool <<<NN / NPB, 128>>>(W2, b2, bat);
    k_fc     <<<(NG * 2 + 255) / 256, 256>>>(Wfc, bfc, out);
}

// round 10
// speedup vs baseline: 1.8847x; 1.0230x over previous
#include <cuda_runtime.h>

#define NN 100000
#define NE 1600000
#define NG 1000
#define F1 64
#define F2 128
#define P0 8
#define SCAN_B 1024
#define NB_SCAN ((NN + SCAN_B - 1) / SCAN_B)   // 98
#define NPB 80          // nodes per block in l2pool (100000/80 = 1250 exact)

// Scratch (device globals — no allocation allowed)
__device__ int   d_hist[NN];
__device__ int   d_row[NN];
__device__ int   d_cur[NN];
__device__ int   d_bsum[NB_SCAN];
__device__ int   d_csr[NE];
__device__ float d_dinv[NN];
__device__ __align__(16) float d_p0[NN * P0];
__device__ __align__(16) float d_p1[NN * F1];
__device__ __align__(16) float d_acc1[NN * F1];
__device__ __align__(16) float d_pool[NG * F2];
__device__ float d_cntf[NG];

__device__ __forceinline__ float relu(float v) { return v > 0.f ? v : 0.f; }

// ---------------------------------------------------------------------------
// 0) Zero hist / pool / cnt
// ---------------------------------------------------------------------------
__global__ void k_init() {
    int i = blockIdx.x * blockDim.x + threadIdx.x;
    if (i < NN)      d_hist[i] = 0;
    if (i < NG * F2) d_pool[i] = 0.f;
    if (i < NG)      d_cntf[i] = 0.f;
}

// ---------------------------------------------------------------------------
// 1) Histogram of dst (in-degree); 4 edges/thread via int4
// ---------------------------------------------------------------------------
__global__ void k_hist(const int* __restrict__ ei) {
    int i = blockIdx.x * blockDim.x + threadIdx.x;
    if (i * 4 >= NE) return;
    int4 d4 = *reinterpret_cast<const int4*>(&ei[NE + i * 4]);
    atomicAdd(&d_hist[d4.x], 1);
    atomicAdd(&d_hist[d4.y], 1);
    atomicAdd(&d_hist[d4.z], 1);
    atomicAdd(&d_hist[d4.w], 1);
}

// ---------------------------------------------------------------------------
// 2) Per-block exclusive scan of hist -> row (pre-offset) + block sums,
//    FUSED with dinv/p0/cnt generation (hist value already in register;
//    x loads overlap the scan shuffles).
// ---------------------------------------------------------------------------
__global__ void k_scan1(const float* __restrict__ x, const int* __restrict__ batch) {
    __shared__ int wsum[32];
    int tid  = threadIdx.x;              // 1024
    int lane = tid & 31, w = tid >> 5;
    int i = blockIdx.x * SCAN_B + tid;
    bool ok = (i < NN);
    int v = ok ? d_hist[i] : 0;

    // start independent work early: dinv + x loads (overlap scan latency)
    float dv = rsqrtf((float)v + 1.f);   // +1 self loop
    float2 x0, x1, x2;
    if (ok) {
        const float2* xp = reinterpret_cast<const float2*>(x) + i * 3;
        x0 = xp[0]; x1 = xp[1]; x2 = xp[2];
    }

    int incl = v;
#pragma unroll
    for (int off = 1; off < 32; off <<= 1) {
        int t = __shfl_up_sync(0xffffffffu, incl, off);
        if (lane >= off) incl += t;
    }
    if (lane == 31) wsum[w] = incl;
    __syncthreads();
    if (w == 0) {
        int s = wsum[lane];
        int si = s;
#pragma unroll
        for (int off = 1; off < 32; off <<= 1) {
            int t = __shfl_up_sync(0xffffffffu, si, off);
            if (lane >= off) si += t;
        }
        wsum[lane] = si - s;             // exclusive warp offsets
    }
    __syncthreads();
    int woff = wsum[w];
    if (tid == SCAN_B - 1) d_bsum[blockIdx.x] = woff + incl;
    if (!ok) return;
    d_row[i] = incl - v + woff;          // pre-block-offset exclusive scan

    d_dinv[i] = dv;
    float4 a, b;
    a.x = dv * x0.x; a.y = dv * x0.y;
    a.z = dv * x1.x; a.w = dv * x1.y;
    b.x = dv * x2.x; b.y = dv * x2.y;
    b.z = 0.f;       b.w = 0.f;
    *reinterpret_cast<float4*>(&d_p0[i * P0 + 0]) = a;
    *reinterpret_cast<float4*>(&d_p0[i * P0 + 4]) = b;
    atomicAdd(&d_cntf[batch[i]], 1.f);
}

// ---------------------------------------------------------------------------
// 3) Tiny row fixup: redundant shfl-scan of 98 block sums, then
//    row += soff;  cur = row.   (pure streaming, ~1.2 MB)
// ---------------------------------------------------------------------------
__global__ void k_scan3() {
    __shared__ int wsum4[4];
    __shared__ int soff[128];
    int tid = threadIdx.x;               // 256
    int incl = 0, v = 0;
    if (tid < 128) {
        v = (tid < NB_SCAN) ? d_bsum[tid] : 0;
        incl = v;
        int lane = tid & 31;
#pragma unroll
        for (int off = 1; off < 32; off <<= 1) {
            int t = __shfl_up_sync(0xffffffffu, incl, off);
            if (lane >= off) incl += t;
        }
        if (lane == 31) wsum4[tid >> 5] = incl;
    }
    __syncthreads();
    if (tid < 128) {
        int w = tid >> 5;
        int add = 0;
#pragma unroll
        for (int k = 0; k < 4; k++) add += (k < w) ? wsum4[k] : 0;
        soff[tid] = incl - v + add;      // exclusive scan of bsum
    }
    __syncthreads();
    int n = blockIdx.x * blockDim.x + tid;
    if (n >= NN) return;
    int r = d_row[n] + soff[n >> 10];
    d_row[n] = r;
    d_cur[n] = r;
}

// ---------------------------------------------------------------------------
// 4) CSR fill: csr[pos] = src, grouped by dst; 4 edges/thread via int4
// ---------------------------------------------------------------------------
__global__ void k_fill(const int* __restrict__ ei) {
    int i = blockIdx.x * blockDim.x + threadIdx.x;
    if (i * 4 >= NE) return;
    int4 s4 = *reinterpret_cast<const int4*>(&ei[i * 4]);
    int4 d4 = *reinterpret_cast<const int4*>(&ei[NE + i * 4]);
    d_csr[atomicAdd(&d_cur[d4.x], 1)] = s4.x;
    d_csr[atomicAdd(&d_cur[d4.y], 1)] = s4.y;
    d_csr[atomicAdd(&d_cur[d4.z], 1)] = s4.z;
    d_csr[atomicAdd(&d_cur[d4.w], 1)] = s4.w;
}

// ---------------------------------------------------------------------------
// 5) Fused PULL0 + L1: t = p0[n] + sum_in p0[s];
//    p1 = dinv * relu(dinv*(t@W1) + b1).  One thread per node.
// ---------------------------------------------------------------------------
__global__ void k_pull0l1(const float* __restrict__ W1, const float* __restrict__ b1) {
    __shared__ float w[6 * F1];
    __shared__ float bs[F1];
    for (int j = threadIdx.x; j < 6 * F1; j += blockDim.x) w[j] = W1[j];
    if (threadIdx.x < F1) bs[threadIdx.x] = b1[threadIdx.x];
    __syncthreads();
    int n = blockIdx.x * blockDim.x + threadIdx.x;
    if (n >= NN) return;
    int start = d_row[n];
    int deg   = d_hist[n];
    float4 a = *reinterpret_cast<const float4*>(&d_p0[n * P0 + 0]);
    float4 b = *reinterpret_cast<const float4*>(&d_p0[n * P0 + 4]);
    for (int j = 0; j < deg; j++) {
        int s = d_csr[start + j];
        float4 u = *reinterpret_cast<const float4*>(&d_p0[s * P0 + 0]);
        float4 v = *reinterpret_cast<const float4*>(&d_p0[s * P0 + 4]);
        a.x += u.x; a.y += u.y; a.z += u.z; a.w += u.w;
        b.x += v.x; b.y += v.y;
    }
    float t[6] = {a.x, a.y, a.z, a.w, b.x, b.y};
    float dv = d_dinv[n];
#pragma unroll
    for (int j = 0; j < 16; j++) {
        float4 o;
        float* po = (float*)&o;
#pragma unroll
        for (int c = 0; c < 4; c++) {
            int idx = j * 4 + c;
            float acc = 0.f;
#pragma unroll
            for (int k = 0; k < 6; k++) acc += t[k] * w[k * F1 + idx];
            po[c] = dv * relu(dv * acc + bs[idx]);
        }
        *reinterpret_cast<float4*>(&d_p1[n * F1 + j * 4]) = o;
    }
}

// ---------------------------------------------------------------------------
// 6) PULL layer 1: acc1[n] = p1[n] + sum_in p1[s].  Warp per node,
//    lane covers feats {lane, lane+32}; unroll-by-4 for MLP.
// ---------------------------------------------------------------------------
__global__ void k_pull1() {
    int wid  = (blockIdx.x * blockDim.x + threadIdx.x) >> 5;
    int lane = threadIdx.x & 31;
    if (wid >= NN) return;
    int n = wid;
    int start = d_row[n];
    int deg   = d_hist[n];
    float a0 = d_p1[n * F1 + lane];
    float a1 = d_p1[n * F1 + 32 + lane];
    int j = 0;
    for (; j + 4 <= deg; j += 4) {
        int s0 = d_csr[start + j];
        int s1 = d_csr[start + j + 1];
        int s2 = d_csr[start + j + 2];
        int s3 = d_csr[start + j + 3];
        float u0 = d_p1[s0 * F1 + lane];
        float u1 = d_p1[s0 * F1 + 32 + lane];
        float v0 = d_p1[s1 * F1 + lane];
        float v1 = d_p1[s1 * F1 + 32 + lane];
        float w0 = d_p1[s2 * F1 + lane];
        float w1 = d_p1[s2 * F1 + 32 + lane];
        float x0 = d_p1[s3 * F1 + lane];
        float x1 = d_p1[s3 * F1 + 32 + lane];
        a0 += (u0 + v0) + (w0 + x0);
        a1 += (u1 + v1) + (w1 + x1);
    }
    for (; j < deg; j++) {
        int s0 = d_csr[start + j];
        a0 += d_p1[s0 * F1 + lane];
        a1 += d_p1[s0 * F1 + 32 + lane];
    }
    d_acc1[n * F1 + lane]      = a0;
    d_acc1[n * F1 + 32 + lane] = a1;
}

// ---------------------------------------------------------------------------
// 7) out2 = relu(dinv*(acc1@W2) + b2), pooled.  Packed f32x2 (two nodes per
//    lane-pair), weights duplicated in regs; 80 nodes/block.
// ---------------------------------------------------------------------------
__global__ void k_l2pool(const float* __restrict__ W2, const float* __restrict__ b2,
                         const int* __restrict__ batch) {
    __shared__ float2 inp[NPB / 2][F1];   // 20 KB
    __shared__ float dv_s[NPB];
    __shared__ int   bt_s[NPB];
    int tid = threadIdx.x;                // output feature 0..127
    unsigned long long wp[F1];
#pragma unroll
    for (int k = 0; k < F1; k++) {
        float wv = W2[k * F2 + tid];
        asm("mov.b64 %0, {%1, %1};" : "=l"(wp[k]) : "f"(wv));
    }
    float bb = b2[tid];
    int base = blockIdx.x * NPB;
    for (int i = tid; i < NPB * F1; i += 128) {
        int nl = i >> 6, k = i & 63;
        reinterpret_cast<float*>(&inp[nl >> 1][k])[nl & 1] = d_acc1[(base + nl) * F1 + k];
    }
    if (tid < NPB) {
        dv_s[tid] = d_dinv[base + tid];
        bt_s[tid] = batch[base + tid];
    }
    __syncthreads();
    float pacc = 0.f;
    int cgid = bt_s[0];
    for (int p = 0; p < NPB / 2; p++) {
        unsigned long long acc = 0ull;    // (0.f, 0.f)
        const ulonglong2* ip = reinterpret_cast<const ulonglong2*>(&inp[p][0]);
#pragma unroll
        for (int k = 0; k < F1; k += 2) {
            ulonglong2 pv = ip[k >> 1];   // LDS.128: two packed k's
            asm("fma.rn.f32x2 %0, %1, %2, %3;" : "=l"(acc) : "l"(wp[k]),     "l"(pv.x), "l"(acc));
            asm("fma.rn.f32x2 %0, %1, %2, %3;" : "=l"(acc) : "l"(wp[k + 1]), "l"(pv.y), "l"(acc));
        }
        float a0, a1;
        asm("mov.b64 {%0, %1}, %2;" : "=f"(a0), "=f"(a1) : "l"(acc));
        int n0 = 2 * p, n1 = 2 * p + 1;
        int g0 = bt_s[n0];
        if (g0 != cgid) { atomicAdd(&d_pool[cgid * F2 + tid], pacc); pacc = 0.f; cgid = g0; }
        pacc += relu(dv_s[n0] * a0 + bb);
        int g1 = bt_s[n1];
        if (g1 != cgid) { atomicAdd(&d_pool[cgid * F2 + tid], pacc); pacc = 0.f; cgid = g1; }
        pacc += relu(dv_s[n1] * a1 + bb);
    }
    atomicAdd(&d_pool[cgid * F2 + tid], pacc);
}

// ---------------------------------------------------------------------------
// 8) out[g] = (pool[g]/max(cnt,1)) @ Wfc + bfc      [1000, 2]
// ---------------------------------------------------------------------------
__global__ void k_fc(const float* __restrict__ Wfc, const float* __restrict__ bfc,
                     float* __restrict__ out) {
    int i = blockIdx.x * blockDim.x + threadIdx.x;
    if (i >= NG * 2) return;
    int g = i >> 1;
    int o = i & 1;
    float cnt = d_cntf[g];
    float inv = 1.f / (cnt > 1.f ? cnt : 1.f);
    float a = 0.f;
#pragma unroll 8
    for (int k = 0; k < F2; k++) a += d_pool[g * F2 + k] * Wfc[k * 2 + o];
    out[i] = a * inv + bfc[o];
}

// ---------------------------------------------------------------------------
extern "C" void kernel_launch(void* const* d_in, const int* in_sizes, int n_in,
                              void* d_out, int out_size) {
    const float* x   = (const float*)d_in[0];
    const int*   ei  = (const int*)d_in[1];   // int32 (JAX x64 disabled)
    const int*   bat = (const int*)d_in[2];   // int32
    const float* W1  = (const float*)d_in[3];
    const float* b1  = (const float*)d_in[4];
    const float* W2  = (const float*)d_in[5];
    const float* b2  = (const float*)d_in[6];
    const float* Wfc = (const float*)d_in[7];
    const float* bfc = (const float*)d_in[8];
    float*       out = (float*)d_out;

    k_init   <<<(NG * F2 + 255) / 256, 256>>>();
    k_hist   <<<(NE / 4 + 255) / 256, 256>>>(ei);
    k_scan1  <<<NB_SCAN, SCAN_B>>>(x, bat);
    k_scan3  <<<(NN + 255) / 256, 256>>>();
    k_fill   <<<(NE / 4 + 255) / 256, 256>>>(ei);
    k_pull0l1<<<(NN + 255) / 256, 256>>>(W1, b1);
    k_pull1  <<<(NN * 32 + 255) / 256, 256>>>();
    k_l2pool <<<NN / NPB, 128>>>(W2, b2, bat);
    k_fc     <<<(NG * 2 + 255) / 256, 256>>>(Wfc, bfc, out);
}

// round 11
// speedup vs baseline: 1.9996x; 1.0610x over previous
#include <cuda_runtime.h>
#include <cuda_fp16.h>

#define NN 100000
#define NE 1600000
#define NG 1000
#define F1 64
#define F2 128
#define P0 8
#define SCAN_B 1024
#define NB_SCAN ((NN + SCAN_B - 1) / SCAN_B)   // 98
#define NPB 80          // nodes per block in l2pool (100000/80 = 1250 exact)

// Scratch (device globals — no allocation allowed)
__device__ int   d_hist[NN];
__device__ int   d_row[NN];
__device__ int   d_cur[NN];
__device__ int   d_bsum[NB_SCAN];
__device__ int   d_csr[NE];
__device__ float d_dinv[NN];
__device__ __align__(16) float   d_p0[NN * P0];
__device__ __align__(16) __half2 d_p1h[NN * (F1 / 2)];   // fp16 messages, 128B/node
__device__ __align__(16) float   d_acc1[NN * F1];
__device__ __align__(16) float   d_pool[NG * F2];
__device__ float d_cntf[NG];

__device__ __forceinline__ float relu(float v) { return v > 0.f ? v : 0.f; }

// ---------------------------------------------------------------------------
// 0) Zero hist / pool / cnt
// ---------------------------------------------------------------------------
__global__ void k_init() {
    int i = blockIdx.x * blockDim.x + threadIdx.x;
    if (i < NN)      d_hist[i] = 0;
    if (i < NG * F2) d_pool[i] = 0.f;
    if (i < NG)      d_cntf[i] = 0.f;
}

// ---------------------------------------------------------------------------
// 1) Histogram of dst (in-degree); 4 edges/thread via int4
// ---------------------------------------------------------------------------
__global__ void k_hist(const int* __restrict__ ei) {
    int i = blockIdx.x * blockDim.x + threadIdx.x;
    if (i * 4 >= NE) return;
    int4 d4 = *reinterpret_cast<const int4*>(&ei[NE + i * 4]);
    atomicAdd(&d_hist[d4.x], 1);
    atomicAdd(&d_hist[d4.y], 1);
    atomicAdd(&d_hist[d4.z], 1);
    atomicAdd(&d_hist[d4.w], 1);
}

// ---------------------------------------------------------------------------
// 2) Per-block exclusive scan of hist -> row (pre-offset) + block sums,
//    FUSED with dinv/p0/cnt generation.
// ---------------------------------------------------------------------------
__global__ void k_scan1(const float* __restrict__ x, const int* __restrict__ batch) {
    __shared__ int wsum[32];
    int tid  = threadIdx.x;              // 1024
    int lane = tid & 31, w = tid >> 5;
    int i = blockIdx.x * SCAN_B + tid;
    bool ok = (i < NN);
    int v = ok ? d_hist[i] : 0;

    // independent work early: dinv + x loads (overlap scan latency)
    float dv = rsqrtf((float)v + 1.f);   // +1 self loop
    float2 x0, x1, x2;
    if (ok) {
        const float2* xp = reinterpret_cast<const float2*>(x) + i * 3;
        x0 = xp[0]; x1 = xp[1]; x2 = xp[2];
    }

    int incl = v;
#pragma unroll
    for (int off = 1; off < 32; off <<= 1) {
        int t = __shfl_up_sync(0xffffffffu, incl, off);
        if (lane >= off) incl += t;
    }
    if (lane == 31) wsum[w] = incl;
    __syncthreads();
    if (w == 0) {
        int s = wsum[lane];
        int si = s;
#pragma unroll
        for (int off = 1; off < 32; off <<= 1) {
            int t = __shfl_up_sync(0xffffffffu, si, off);
            if (lane >= off) si += t;
        }
        wsum[lane] = si - s;             // exclusive warp offsets
    }
    __syncthreads();
    int woff = wsum[w];
    if (tid == SCAN_B - 1) d_bsum[blockIdx.x] = woff + incl;
    if (!ok) return;
    d_row[i] = incl - v + woff;          // pre-block-offset exclusive scan

    d_dinv[i] = dv;
    float4 a, b;
    a.x = dv * x0.x; a.y = dv * x0.y;
    a.z = dv * x1.x; a.w = dv * x1.y;
    b.x = dv * x2.x; b.y = dv * x2.y;
    b.z = 0.f;       b.w = 0.f;
    *reinterpret_cast<float4*>(&d_p0[i * P0 + 0]) = a;
    *reinterpret_cast<float4*>(&d_p0[i * P0 + 4]) = b;
    atomicAdd(&d_cntf[batch[i]], 1.f);
}

// ---------------------------------------------------------------------------
// 3) Row fixup: redundant shfl-scan of 98 block sums; row += soff; cur = row
// ---------------------------------------------------------------------------
__global__ void k_scan3() {
    __shared__ int wsum4[4];
    __shared__ int soff[128];
    int tid = threadIdx.x;               // 256
    int incl = 0, v = 0;
    if (tid < 128) {
        v = (tid < NB_SCAN) ? d_bsum[tid] : 0;
        incl = v;
        int lane = tid & 31;
#pragma unroll
        for (int off = 1; off < 32; off <<= 1) {
            int t = __shfl_up_sync(0xffffffffu, incl, off);
            if (lane >= off) incl += t;
        }
        if (lane == 31) wsum4[tid >> 5] = incl;
    }
    __syncthreads();
    if (tid < 128) {
        int w = tid >> 5;
        int add = 0;
#pragma unroll
        for (int k = 0; k < 4; k++) add += (k < w) ? wsum4[k] : 0;
        soff[tid] = incl - v + add;
    }
    __syncthreads();
    int n = blockIdx.x * blockDim.x + tid;
    if (n >= NN) return;
    int r = d_row[n] + soff[n >> 10];
    d_row[n] = r;
    d_cur[n] = r;
}

// ---------------------------------------------------------------------------
// 4) CSR fill: csr[pos] = src, grouped by dst; 4 edges/thread via int4
// ---------------------------------------------------------------------------
__global__ void k_fill(const int* __restrict__ ei) {
    int i = blockIdx.x * blockDim.x + threadIdx.x;
    if (i * 4 >= NE) return;
    int4 s4 = *reinterpret_cast<const int4*>(&ei[i * 4]);
    int4 d4 = *reinterpret_cast<const int4*>(&ei[NE + i * 4]);
    d_csr[atomicAdd(&d_cur[d4.x], 1)] = s4.x;
    d_csr[atomicAdd(&d_cur[d4.y], 1)] = s4.y;
    d_csr[atomicAdd(&d_cur[d4.z], 1)] = s4.z;
    d_csr[atomicAdd(&d_cur[d4.w], 1)] = s4.w;
}

// ---------------------------------------------------------------------------
// 5) Fused PULL0 + L1: t = p0[n] + sum_in p0[s];
//    p1 = fp16( dinv * relu(dinv*(t@W1) + b1) ).  One thread per node.
// ---------------------------------------------------------------------------
__global__ void k_pull0l1(const float* __restrict__ W1, const float* __restrict__ b1) {
    __shared__ float w[6 * F1];
    __shared__ float bs[F1];
    for (int j = threadIdx.x; j < 6 * F1; j += blockDim.x) w[j] = W1[j];
    if (threadIdx.x < F1) bs[threadIdx.x] = b1[threadIdx.x];
    __syncthreads();
    int n = blockIdx.x * blockDim.x + threadIdx.x;
    if (n >= NN) return;
    int start = d_row[n];
    int deg   = d_hist[n];
    float4 a = *reinterpret_cast<const float4*>(&d_p0[n * P0 + 0]);
    float4 b = *reinterpret_cast<const float4*>(&d_p0[n * P0 + 4]);
    for (int j = 0; j < deg; j++) {
        int s = d_csr[start + j];
        float4 u = *reinterpret_cast<const float4*>(&d_p0[s * P0 + 0]);
        float4 v = *reinterpret_cast<const float4*>(&d_p0[s * P0 + 4]);
        a.x += u.x; a.y += u.y; a.z += u.z; a.w += u.w;
        b.x += v.x; b.y += v.y;
    }
    float t[6] = {a.x, a.y, a.z, a.w, b.x, b.y};
    float dv = d_dinv[n];
#pragma unroll
    for (int j = 0; j < 16; j++) {       // 4 feats per iter -> 2 half2 (8B store)
        float o[4];
#pragma unroll
        for (int c = 0; c < 4; c++) {
            int idx = j * 4 + c;
            float acc = 0.f;
#pragma unroll
            for (int k = 0; k < 6; k++) acc += t[k] * w[k * F1 + idx];
            o[c] = dv * relu(dv * acc + bs[idx]);
        }
        __half2 h0 = __floats2half2_rn(o[0], o[1]);
        __half2 h1 = __floats2half2_rn(o[2], o[3]);
        __half2* dst = &d_p1h[n * (F1 / 2) + j * 2];
        *reinterpret_cast<uint2*>(dst) = make_uint2(
            *reinterpret_cast<unsigned*>(&h0), *reinterpret_cast<unsigned*>(&h1));
    }
}

// ---------------------------------------------------------------------------
// 6) PULL layer 1: acc1[n] = p1[n] + sum_in p1[s].  Warp per node.
//    fp16 rows = 128B/node -> ONE cache line per edge gather; lane reads one
//    half2 (feats {2*lane, 2*lane+1}), accumulates in fp32. Unroll-by-4.
// ---------------------------------------------------------------------------
__global__ void k_pull1() {
    int wid  = (blockIdx.x * blockDim.x + threadIdx.x) >> 5;
    int lane = threadIdx.x & 31;
    if (wid >= NN) return;
    int n = wid;
    int start = d_row[n];
    int deg   = d_hist[n];
    const __half2* p = d_p1h;
    float2 acc = __half22float2(p[n * 32 + lane]);
    int j = 0;
    for (; j + 4 <= deg; j += 4) {
        int s0 = d_csr[start + j];
        int s1 = d_csr[start + j + 1];
        int s2 = d_csr[start + j + 2];
        int s3 = d_csr[start + j + 3];
        float2 u0 = __half22float2(p[s0 * 32 + lane]);
        float2 u1 = __half22float2(p[s1 * 32 + lane]);
        float2 u2 = __half22float2(p[s2 * 32 + lane]);
        float2 u3 = __half22float2(p[s3 * 32 + lane]);
        acc.x += (u0.x + u1.x) + (u2.x + u3.x);
        acc.y += (u0.y + u1.y) + (u2.y + u3.y);
    }
    for (; j < deg; j++) {
        int s0 = d_csr[start + j];
        float2 u = __half22float2(p[s0 * 32 + lane]);
        acc.x += u.x;
        acc.y += u.y;
    }
    *reinterpret_cast<float2*>(&d_acc1[n * F1 + 2 * lane]) = acc;
}

// ---------------------------------------------------------------------------
// 7) out2 = relu(dinv*(acc1@W2) + b2), pooled.  Packed f32x2 (two nodes per
//    lane-pair), weights duplicated in regs; 80 nodes/block.
// ---------------------------------------------------------------------------
__global__ void k_l2pool(const float* __restrict__ W2, const float* __restrict__ b2,
                         const int* __restrict__ batch) {
    __shared__ float2 inp[NPB / 2][F1];   // 20 KB
    __shared__ float dv_s[NPB];
    __shared__ int   bt_s[NPB];
    int tid = threadIdx.x;                // output feature 0..127
    unsigned long long wp[F1];
#pragma unroll
    for (int k = 0; k < F1; k++) {
        float wv = W2[k * F2 + tid];
        asm("mov.b64 %0, {%1, %1};" : "=l"(wp[k]) : "f"(wv));
    }
    float bb = b2[tid];
    int base = blockIdx.x * NPB;
    for (int i = tid; i < NPB * F1; i += 128) {
        int nl = i >> 6, k = i & 63;
        reinterpret_cast<float*>(&inp[nl >> 1][k])[nl & 1] = d_acc1[(base + nl) * F1 + k];
    }
    if (tid < NPB) {
        dv_s[tid] = d_dinv[base + tid];
        bt_s[tid] = batch[base + tid];
    }
    __syncthreads();
    float pacc = 0.f;
    int cgid = bt_s[0];
    for (int p = 0; p < NPB / 2; p++) {
        unsigned long long acc = 0ull;    // (0.f, 0.f)
        const ulonglong2* ip = reinterpret_cast<const ulonglong2*>(&inp[p][0]);
#pragma unroll
        for (int k = 0; k < F1; k += 2) {
            ulonglong2 pv = ip[k >> 1];   // LDS.128: two packed k's
            asm("fma.rn.f32x2 %0, %1, %2, %3;" : "=l"(acc) : "l"(wp[k]),     "l"(pv.x), "l"(acc));
            asm("fma.rn.f32x2 %0, %1, %2, %3;" : "=l"(acc) : "l"(wp[k + 1]), "l"(pv.y), "l"(acc));
        }
        float a0, a1;
        asm("mov.b64 {%0, %1}, %2;" : "=f"(a0), "=f"(a1) : "l"(acc));
        int n0 = 2 * p, n1 = 2 * p + 1;
        int g0 = bt_s[n0];
        if (g0 != cgid) { atomicAdd(&d_pool[cgid * F2 + tid], pacc); pacc = 0.f; cgid = g0; }
        pacc += relu(dv_s[n0] * a0 + bb);
        int g1 = bt_s[n1];
        if (g1 != cgid) { atomicAdd(&d_pool[cgid * F2 + tid], pacc); pacc = 0.f; cgid = g1; }
        pacc += relu(dv_s[n1] * a1 + bb);
    }
    atomicAdd(&d_pool[cgid * F2 + tid], pacc);
}

// ---------------------------------------------------------------------------
// 8) out[g] = (pool[g]/max(cnt,1)) @ Wfc + bfc      [1000, 2]
// ---------------------------------------------------------------------------
__global__ void k_fc(const float* __restrict__ Wfc, const float* __restrict__ bfc,
                     float* __restrict__ out) {
    int i = blockIdx.x * blockDim.x + threadIdx.x;
    if (i >= NG * 2) return;
    int g = i >> 1;
    int o = i & 1;
    float cnt = d_cntf[g];
    float inv = 1.f / (cnt > 1.f ? cnt : 1.f);
    float a = 0.f;
#pragma unroll 8
    for (int k = 0; k < F2; k++) a += d_pool[g * F2 + k] * Wfc[k * 2 + o];
    out[i] = a * inv + bfc[o];
}

// ---------------------------------------------------------------------------
extern "C" void kernel_launch(void* const* d_in, const int* in_sizes, int n_in,
                              void* d_out, int out_size) {
    const float* x   = (const float*)d_in[0];
    const int*   ei  = (const int*)d_in[1];   // int32 (JAX x64 disabled)
    const int*   bat = (const int*)d_in[2];   // int32
    const float* W1  = (const float*)d_in[3];
    const float* b1  = (const float*)d_in[4];
    const float* W2  = (const float*)d_in[5];
    const float* b2  = (const float*)d_in[6];
    const float* Wfc = (const float*)d_in[7];
    const float* bfc = (const float*)d_in[8];
    float*       out = (float*)d_out;

    k_init   <<<(NG * F2 + 255) / 256, 256>>>();
    k_hist   <<<(NE / 4 + 255) / 256, 256>>>(ei);
    k_scan1  <<<NB_SCAN, SCAN_B>>>(x, bat);
    k_scan3  <<<(NN + 255) / 256, 256>>>();
    k_fill   <<<(NE / 4 + 255) / 256, 256>>>(ei);
    k_pull0l1<<<(NN + 255) / 256, 256>>>(W1, b1);
    k_pull1  <<<(NN * 32 + 255) / 256, 256>>>();
    k_l2pool <<<NN / NPB, 128>>>(W2, b2, bat);
    k_fc     <<<(NG * 2 + 255) / 256, 256>>>(Wfc, bfc, out);
}